// round 14
// baseline (speedup 1.0000x reference)
#include <cuda_runtime.h>
#include <cuda_bf16.h>
#include <cstdint>

// Problem constants
#define SD      16384        // S*D
#define NJ      22           // 14 alpha cols + 8 beta cols
#define NJP     24           // padded (2 zero cols)
#define BN      2048         // B*N
#define KC      8            // k-chunks (2048 floats each, == s)
#define MT      16           // m-tiles of 128 bn
#define NTILE   32           // 64-k tiles per chunk
#define KT_TOT  256          // total 64-k tiles (SD/64)

typedef unsigned long long ull;

// g_Wf: B operand pre-baked in mma.m16n8k16 B-fragment layout (R8 layout).
// [kt][ks 0..3][ng 0..2][lane 0..31] -> uint2 {b0, b1}:
//   j = ng*8 + lane/4,  k0 = kt*64 + ks*16 + (lane%4)*2
//   b0 = bf16x2( w[j][k0],   w[j][k0+1] )
//   b1 = bf16x2( w[j][k0+8], w[j][k0+9] )
// with w[j][k] = (gamma[k]+1) * W[k][j], j>=22 -> 0.
__device__ __align__(16) uint2 g_Wf[KT_TOT * 12 * 32];
__device__ float g_part[KC][BN][NJP];
__device__ float g_ss[KC][BN];
__device__ float g_M[BN * 64];

__device__ __forceinline__ uint32_t pack_bf16x2(float lo, float hi) {
    __nv_bfloat162 h = __float22bfloat162_rn(make_float2(lo, hi));
    return *reinterpret_cast<uint32_t*>(&h);
}
__device__ __forceinline__ uint32_t smem_u32(const void* p) {
    uint32_t a;
    asm("{ .reg .u64 t; cvta.to.shared.u64 t, %1; cvt.u32.u64 %0, t; }" : "=r"(a) : "l"(p));
    return a;
}
__device__ __forceinline__ void ldsm_x4(uint32_t* a, uint32_t saddr) {
    asm volatile(
        "ldmatrix.sync.aligned.m8n8.x4.shared.b16 {%0,%1,%2,%3}, [%4];"
        : "=r"(a[0]), "=r"(a[1]), "=r"(a[2]), "=r"(a[3]) : "r"(saddr));
}
__device__ __forceinline__ void mma_bf16(float* d, const uint32_t* a, uint2 b) {
    asm volatile(
        "mma.sync.aligned.m16n8k16.row.col.f32.bf16.bf16.f32 "
        "{%0,%1,%2,%3}, {%4,%5,%6,%7}, {%8,%9}, {%0,%1,%2,%3};"
        : "+f"(d[0]), "+f"(d[1]), "+f"(d[2]), "+f"(d[3])
        : "r"(a[0]), "r"(a[1]), "r"(a[2]), "r"(a[3]), "r"(b.x), "r"(b.y));
}

// ---------------------------------------------------------------------------
// Kernel P: bake B fragments (gamma folded, bf16). One thread per uint2.
// (identical to the R8 best)
// ---------------------------------------------------------------------------
__global__ void k_prepW(const float* __restrict__ gamma,
                        const float* __restrict__ Wa,
                        const float* __restrict__ Wb) {
    int i = blockIdx.x * blockDim.x + threadIdx.x;
    if (i >= KT_TOT * 12 * 32) return;
    int kt   = i / 384;
    int rem  = i - kt * 384;
    int ks   = rem / 96;
    int ng   = (rem / 32) % 3;
    int lane = rem & 31;
    int quad = lane >> 2, pos = lane & 3;
    int j  = ng * 8 + quad;
    int k0 = kt * 64 + ks * 16 + pos * 2;

    float w[4] = {0.f, 0.f, 0.f, 0.f};
    if (j < 22) {
        #pragma unroll
        for (int e = 0; e < 4; e++) {
            int k = k0 + (e >> 1) * 8 + (e & 1);
            float ww = (j < 14) ? Wa[(size_t)k * 14 + j] : Wb[(size_t)k * 8 + (j - 14)];
            w[e] = (gamma[k] + 1.0f) * ww;
        }
    }
    g_Wf[i] = make_uint2(pack_bf16x2(w[0], w[1]), pack_bf16x2(w[2], w[3]));
}

// ---------------------------------------------------------------------------
// Kernel A: bf16 mma.sync reductions with coalesced loads + ldmatrix staging.
// grid=(MT, KC) = 128 CTAs, 256 threads. Warp w owns rows [w*16, w*16+16)
// of the 128-bn m-tile, scanning 2048 k. Per 64-k tile:
//   8x LDG.128, each covering TWO complete 256B rows (fully coalesced,
//   4 wavefronts/instr vs 8 for the old scattered LDG.64 pattern),
//   fp32 sumsq + cvt->bf16, 8x swizzled STS.64 into a 2KB/warp smem tile,
//   4x ldmatrix.m8n8.x4 -> A fragments, 12x mma. B fragments as in R8.
// ---------------------------------------------------------------------------
__global__ __launch_bounds__(256) void k_reduce(const float* __restrict__ resid) {
    __shared__ __align__(16) char smem[8][2048];   // 16x64 bf16 tile per warp
    const int warp = threadIdx.x >> 5;
    const int lane = threadIdx.x & 31;
    const int quad = lane >> 2, pos = lane & 3;
    const int mt = blockIdx.x, c = blockIdx.y;
    const int b = mt >> 3, nbase = (mt & 7) * 128;

    const float4* r4 = reinterpret_cast<const float4*>(resid);
    const uint32_t base_f4 = (uint32_t)b * 4194304u + (uint32_t)c * 524288u
                           + (uint32_t)(nbase + warp * 16) * 512u;
    const int lrow = lane >> 4;            // 0/1: which of the instr's 2 rows
    const int kf   = lane & 15;            // float4 index within the row's 64 k

    const uint32_t swarp = smem_u32(&smem[warp][0]);

    // STS addresses (fixed across tiles): row = 2i+lrow, 16B unit u = kf>>1,
    // swizzled u' = u ^ (row&7); byte = row*128 + u'*16 + (kf&1)*8
    uint32_t sts_ad[8];
    #pragma unroll
    for (int i = 0; i < 8; i++) {
        int row = 2 * i + lrow;
        sts_ad[i] = swarp + (uint32_t)(row * 128 + (((kf >> 1) ^ (row & 7)) << 4)
                                       + ((kf & 1) << 3));
    }
    // ldmatrix addresses per ks: m = lane>>3, rr = lane&7, row16 = rr + (m&1)*8,
    // 16B unit v = ks*2 + (m>>1); byte = row16*128 + (v ^ (row16&7))*16
    uint32_t lds_ad[4];
    {
        int m = lane >> 3, rr = lane & 7;
        int row16 = rr + (m & 1) * 8;
        #pragma unroll
        for (int ks = 0; ks < 4; ks++) {
            int v = ks * 2 + (m >> 1);
            lds_ad[ks] = swarp + (uint32_t)(row16 * 128 + ((v ^ (row16 & 7)) << 4));
        }
    }

    float acc[3][4];
    #pragma unroll
    for (int ng = 0; ng < 3; ng++)
        #pragma unroll
        for (int e = 0; e < 4; e++) acc[ng][e] = 0.0f;
    float ss[8];
    #pragma unroll
    for (int i = 0; i < 8; i++) ss[i] = 0.0f;

    #pragma unroll 1
    for (int t = 0; t < NTILE; t++) {
        // coalesced A loads: instr i covers rows 2i,2i+1 fully (512B contig)
        float4 rv[8];
        const uint32_t tb = base_f4 + (uint32_t)t * 16u + (uint32_t)lrow * 512u
                          + (uint32_t)kf;
        #pragma unroll
        for (int i = 0; i < 8; i++)
            rv[i] = r4[tb + (uint32_t)i * 1024u];

        __syncwarp();   // previous tile's ldmatrix reads done before overwrite
        #pragma unroll
        for (int i = 0; i < 8; i++) {
            float4 v = rv[i];
            ss[i] = fmaf(v.x, v.x, ss[i]);
            ss[i] = fmaf(v.y, v.y, ss[i]);
            ss[i] = fmaf(v.z, v.z, ss[i]);
            ss[i] = fmaf(v.w, v.w, ss[i]);
            uint2 pk = make_uint2(pack_bf16x2(v.x, v.y), pack_bf16x2(v.z, v.w));
            asm volatile("st.shared.v2.b32 [%0], {%1, %2};"
                         :: "r"(sts_ad[i]), "r"(pk.x), "r"(pk.y));
        }
        __syncwarp();

        // B fragments (L1/L2-hot, shared by all warps/CTAs)
        uint2 bv[12];
        const uint2* wt = g_Wf + (size_t)(c * NTILE + t) * 384 + lane;
        #pragma unroll
        for (int i = 0; i < 12; i++) bv[i] = wt[i * 32];

        #pragma unroll
        for (int ks = 0; ks < 4; ks++) {
            uint32_t a[4];
            ldsm_x4(a, lds_ad[ks]);
            #pragma unroll
            for (int ng = 0; ng < 3; ng++)
                mma_bf16(acc[ng], a, bv[ks * 3 + ng]);
        }
    }

    // store dot partials: D frag (m16n8): c0,c1 -> row quad, cols pos*2,+1
    const int bn0 = mt * 128 + warp * 16;
    #pragma unroll
    for (int ng = 0; ng < 3; ng++) {
        const int j0 = ng * 8 + pos * 2;
        *reinterpret_cast<float2*>(&g_part[c][bn0 + quad][j0]) =
            make_float2(acc[ng][0], acc[ng][1]);
        *reinterpret_cast<float2*>(&g_part[c][bn0 + quad + 8][j0]) =
            make_float2(acc[ng][2], acc[ng][3]);
    }
    // sumsq: ss[i] belongs to row 2i+lrow; reduce across the 16 lanes sharing lrow
    #pragma unroll
    for (int i = 0; i < 8; i++) {
        float v = ss[i];
        #pragma unroll
        for (int o = 1; o < 16; o <<= 1)
            v += __shfl_xor_sync(0xffffffffu, v, o);
        if (kf == 0)
            g_ss[c][bn0 + 2 * i + lrow] = v;
    }
}

// ---------------------------------------------------------------------------
// Kernel B: per-(b,n) scalar epilogue -> 8x8 mixing matrix M
// ---------------------------------------------------------------------------
__global__ void k_mix(const float* __restrict__ salpha,
                      const float* __restrict__ pbs,
                      const float* __restrict__ rscale,
                      const float* __restrict__ sbeta,
                      const float* __restrict__ hps) {
    int bn = blockIdx.x * blockDim.x + threadIdx.x;
    if (bn >= BN) return;

    float dot[NJ];
    #pragma unroll
    for (int j = 0; j < NJ; j++) {
        float v = 0.0f;
        #pragma unroll
        for (int c = 0; c < KC; c++) v += g_part[c][bn][j];
        dot[j] = v;
    }
    float sumsq = 0.0f;
    #pragma unroll
    for (int c = 0; c < KC; c++) sumsq += g_ss[c][bn];

    float scale = rsqrtf(fmaxf(sumsq, 1e-24f)) * 128.0f;  // sqrt(16384)=128
    float ps = pbs[0], rs = rscale[0], hp = hps[0];

    // w_pre = softmax(ps * dyn_pre + static_alpha[:8])
    float l[8], mx = -1e30f;
    #pragma unroll
    for (int i = 0; i < 8; i++) {
        l[i] = ps * (scale * dot[i]) + salpha[i];
        mx = fmaxf(mx, l[i]);
    }
    float e[8], sum = 0.0f;
    #pragma unroll
    for (int i = 0; i < 8; i++) { e[i] = expf(l[i] - mx); sum += e[i]; }
    float inv_sum = 1.0f / sum;
    float wpre[8];
    #pragma unroll
    for (int i = 0; i < 8; i++) wpre[i] = e[i] * inv_sum;

    // pairwise softmax first elements
    float p[3];
    #pragma unroll
    for (int k = 0; k < 3; k++) {
        float c0 = rs * (scale * dot[8 + 2 * k])     + salpha[8 + 2 * k];
        float c1 = rs * (scale * dot[8 + 2 * k + 1]) + salpha[8 + 2 * k + 1];
        p[k] = 1.0f / (1.0f + expf(c1 - c0));
    }
    // Kron: H[s][t] = h[s^t]
    float h[8];
    #pragma unroll
    for (int x = 0; x < 8; x++) {
        float f0 = (x & 4) ? (1.0f - p[0]) : p[0];
        float f1 = (x & 2) ? (1.0f - p[1]) : p[1];
        float f2 = (x & 1) ? (1.0f - p[2]) : p[2];
        h[x] = f0 * f1 * f2;
    }
    float beta[8];
    #pragma unroll
    for (int t = 0; t < 8; t++)
        beta[t] = 1.0f / (1.0f + expf(-(hp * (scale * dot[14 + t]) + sbeta[t])));

    float* Mo = &g_M[bn * 64];
    #pragma unroll
    for (int s = 0; s < 8; s++)
        #pragma unroll
        for (int t = 0; t < 8; t++)
            Mo[s * 8 + t] = h[s ^ t] + beta[t] * wpre[s];
}

// ---------------------------------------------------------------------------
// Kernel C: out[t,d] = sum_s M[s][t] * r[s,d].  grid=(BN, 2). fp32 residuals.
// ---------------------------------------------------------------------------
__global__ __launch_bounds__(256) void k_apply(const float* __restrict__ resid,
                                               float* __restrict__ out) {
    const int bn = blockIdx.x;
    const int b = bn >> 10, n = bn & 1023;

    __shared__ float Ms[64];
    if (threadIdx.x < 64) Ms[threadIdx.x] = g_M[bn * 64 + threadIdx.x];
    __syncthreads();

    float M[64];
    #pragma unroll
    for (int i = 0; i < 64; i++) M[i] = Ms[i];

    const size_t base = (size_t)b * 16777216u + (size_t)n * 2048u;
    const int d = blockIdx.y * 1024 + threadIdx.x * 4;

    float4 acc[8];
    #pragma unroll
    for (int t = 0; t < 8; t++) acc[t] = make_float4(0.f, 0.f, 0.f, 0.f);

    #pragma unroll
    for (int s = 0; s < 8; s++) {
        float4 r4 = *reinterpret_cast<const float4*>(resid + base + (size_t)s * 2097152u + d);
        #pragma unroll
        for (int t = 0; t < 8; t++) {
            float m = M[s * 8 + t];
            acc[t].x += m * r4.x;
            acc[t].y += m * r4.y;
            acc[t].z += m * r4.z;
            acc[t].w += m * r4.w;
        }
    }
    #pragma unroll
    for (int t = 0; t < 8; t++)
        *reinterpret_cast<float4*>(out + base + (size_t)t * 2097152u + d) = acc[t];
}

// ---------------------------------------------------------------------------
extern "C" void kernel_launch(void* const* d_in, const int* in_sizes, int n_in,
                              void* d_out, int out_size) {
    const float* resid  = (const float*)d_in[0];   // residuals (B*S, N, D)
    const float* gamma  = (const float*)d_in[1];   // (S*D,)
    const float* salpha = (const float*)d_in[2];   // (S+T,) = 14
    const float* Wa     = (const float*)d_in[3];   // (S*D, 14)
    const float* pbs    = (const float*)d_in[4];   // (1,)
    const float* rs     = (const float*)d_in[5];   // (1,)
    const float* sbeta  = (const float*)d_in[6];   // (S,) = 8
    const float* Wb     = (const float*)d_in[7];   // (S*D, 8)
    const float* hps    = (const float*)d_in[8];   // scalar
    float* out = (float*)d_out;

    k_prepW<<<(KT_TOT * 12 * 32 + 255) / 256, 256>>>(gamma, Wa, Wb);
    k_reduce<<<dim3(MT, KC), 256>>>(resid);
    k_mix<<<BN / 256, 256>>>(salpha, pbs, rs, sbeta, hps);
    k_apply<<<dim3(BN, 2), 256>>>(resid, out);
}

// round 15
// speedup vs baseline: 1.8365x; 1.8365x over previous
#include <cuda_runtime.h>
#include <cuda_bf16.h>
#include <cstdint>

// Problem constants
#define SD      16384        // S*D
#define NJ      22           // 14 alpha cols + 8 beta cols
#define NJP     24           // padded (2 zero cols)
#define BN      2048         // B*N
#define KC      8            // k-chunks (2048 floats each, == s)
#define MT      16           // m-tiles of 128 bn
#define NTILE   32           // 64-k tiles per chunk
#define KT_TOT  256          // total 64-k tiles (SD/64)

typedef unsigned long long ull;

// g_Wf: B operand pre-baked in mma.m16n8k16 B-fragment layout (R8 layout).
// [kt][ks 0..3][ng 0..2][lane 0..31] -> uint2 {b0, b1}:
//   j = ng*8 + lane/4,  k0 = kt*64 + ks*16 + (lane%4)*2
//   b0 = bf16x2( w[j][k0],   w[j][k0+1] )
//   b1 = bf16x2( w[j][k0+8], w[j][k0+9] )
// with w[j][k] = (gamma[k]+1) * W[k][j], j>=22 -> 0.
__device__ __align__(16) uint2 g_Wf[KT_TOT * 12 * 32];
__device__ float g_part[KC][BN][NJP];
__device__ float g_ss[KC][BN];

__device__ __forceinline__ uint32_t pack_bf16x2(float lo, float hi) {
    __nv_bfloat162 h = __float22bfloat162_rn(make_float2(lo, hi));
    return *reinterpret_cast<uint32_t*>(&h);
}

__device__ __forceinline__ void mma_bf16(float* d, const uint32_t* a, uint2 b) {
    asm volatile(
        "mma.sync.aligned.m16n8k16.row.col.f32.bf16.bf16.f32 "
        "{%0,%1,%2,%3}, {%4,%5,%6,%7}, {%8,%9}, {%0,%1,%2,%3};"
        : "+f"(d[0]), "+f"(d[1]), "+f"(d[2]), "+f"(d[3])
        : "r"(a[0]), "r"(a[1]), "r"(a[2]), "r"(a[3]), "r"(b.x), "r"(b.y));
}

// ---------------------------------------------------------------------------
// Kernel P: bake B fragments (gamma folded, bf16). One thread per uint2.
// (identical to the R8 best)
// ---------------------------------------------------------------------------
__global__ void k_prepW(const float* __restrict__ gamma,
                        const float* __restrict__ Wa,
                        const float* __restrict__ Wb) {
    int i = blockIdx.x * blockDim.x + threadIdx.x;
    if (i >= KT_TOT * 12 * 32) return;
    int kt   = i / 384;
    int rem  = i - kt * 384;
    int ks   = rem / 96;
    int ng   = (rem / 32) % 3;
    int lane = rem & 31;
    int quad = lane >> 2, pos = lane & 3;
    int j  = ng * 8 + quad;
    int k0 = kt * 64 + ks * 16 + pos * 2;

    float w[4] = {0.f, 0.f, 0.f, 0.f};
    if (j < 22) {
        #pragma unroll
        for (int e = 0; e < 4; e++) {
            int k = k0 + (e >> 1) * 8 + (e & 1);
            float ww = (j < 14) ? Wa[(size_t)k * 14 + j] : Wb[(size_t)k * 8 + (j - 14)];
            w[e] = (gamma[k] + 1.0f) * ww;
        }
    }
    g_Wf[i] = make_uint2(pack_bf16x2(w[0], w[1]), pack_bf16x2(w[2], w[3]));
}

// ---------------------------------------------------------------------------
// Kernel A: tensor-core reductions via warp-level bf16 mma.sync.
// (identical to the R8 best: grid=(MT,KC)=128 CTAs, 256 threads, warp owns
// 16 bn rows x 2048 k, no smem, no syncs)
// ---------------------------------------------------------------------------
__global__ __launch_bounds__(256, 1) void k_reduce(const float* __restrict__ resid) {
    const int warp = threadIdx.x >> 5;
    const int lane = threadIdx.x & 31;
    const int quad = lane >> 2, pos = lane & 3;
    const int mt = blockIdx.x, chunk = blockIdx.y;
    const int b = mt >> 3, nbase = (mt & 7) * 128;

    const int row_lo = warp * 16 + quad;       // fragment rows quad / quad+8
    const float2* r2 = reinterpret_cast<const float2*>(resid);
    const size_t off_lo = (size_t)b * 8388608u + (size_t)chunk * 1048576u
                        + (size_t)(nbase + row_lo) * 1024u;
    const size_t off_hi = off_lo + 8u * 1024u;

    float acc[3][4];
    #pragma unroll
    for (int ng = 0; ng < 3; ng++)
        #pragma unroll
        for (int e = 0; e < 4; e++) acc[ng][e] = 0.0f;
    float ss_lo = 0.0f, ss_hi = 0.0f;

    #pragma unroll 1
    for (int t = 0; t < NTILE; t++) {
        // A loads: 16 float2, all independent (MLP=16)
        float2 av[4][4];
        const int kb2 = t * 32 + pos;          // float2 index of k = t*64+pos*2
        #pragma unroll
        for (int ks = 0; ks < 4; ks++) {
            const int c0 = kb2 + ks * 8;
            av[ks][0] = r2[off_lo + c0];
            av[ks][1] = r2[off_hi + c0];
            av[ks][2] = r2[off_lo + c0 + 4];   // k+8
            av[ks][3] = r2[off_hi + c0 + 4];
        }
        // B fragments: 12 coalesced uint2 (L1/L2-resident, shared by all warps)
        uint2 bv[12];
        const uint2* wt = g_Wf + (size_t)(chunk * NTILE + t) * 384 + lane;
        #pragma unroll
        for (int i = 0; i < 12; i++) bv[i] = wt[i * 32];

        #pragma unroll
        for (int ks = 0; ks < 4; ks++) {
            // fp32 sumsq from the same registers
            ss_lo = fmaf(av[ks][0].x, av[ks][0].x, ss_lo);
            ss_lo = fmaf(av[ks][0].y, av[ks][0].y, ss_lo);
            ss_lo = fmaf(av[ks][2].x, av[ks][2].x, ss_lo);
            ss_lo = fmaf(av[ks][2].y, av[ks][2].y, ss_lo);
            ss_hi = fmaf(av[ks][1].x, av[ks][1].x, ss_hi);
            ss_hi = fmaf(av[ks][1].y, av[ks][1].y, ss_hi);
            ss_hi = fmaf(av[ks][3].x, av[ks][3].x, ss_hi);
            ss_hi = fmaf(av[ks][3].y, av[ks][3].y, ss_hi);
            // cvt -> bf16 A fragment
            uint32_t a[4];
            a[0] = pack_bf16x2(av[ks][0].x, av[ks][0].y);
            a[1] = pack_bf16x2(av[ks][1].x, av[ks][1].y);
            a[2] = pack_bf16x2(av[ks][2].x, av[ks][2].y);
            a[3] = pack_bf16x2(av[ks][3].x, av[ks][3].y);
            #pragma unroll
            for (int ng = 0; ng < 3; ng++)
                mma_bf16(acc[ng], a, bv[ks * 3 + ng]);
        }
    }

    // store dot partials: D frag (m16n8): c0,c1 -> row quad, cols pos*2,+1
    const int bn_lo = mt * 128 + row_lo;
    #pragma unroll
    for (int ng = 0; ng < 3; ng++) {
        const int j0 = ng * 8 + pos * 2;
        *reinterpret_cast<float2*>(&g_part[chunk][bn_lo][j0]) =
            make_float2(acc[ng][0], acc[ng][1]);
        *reinterpret_cast<float2*>(&g_part[chunk][bn_lo + 8][j0]) =
            make_float2(acc[ng][2], acc[ng][3]);
    }
    // sumsq: reduce across the 4 lanes sharing this quad
    #pragma unroll
    for (int o = 1; o < 4; o <<= 1) {
        ss_lo += __shfl_xor_sync(0xffffffffu, ss_lo, o, 4);
        ss_hi += __shfl_xor_sync(0xffffffffu, ss_hi, o, 4);
    }
    if (pos == 0) {
        g_ss[chunk][bn_lo]     = ss_lo;
        g_ss[chunk][bn_lo + 8] = ss_hi;
    }
}

// ---------------------------------------------------------------------------
// Kernel C (fused): prologue rebuilds this bn's 8x8 mixing matrix M from the
// partials (k_mix inlined, fixed-order sums -> deterministic), then the
// unchanged R8 apply body: out[t,d] = sum_s M[s][t] * r[s,d]. grid=(BN, 2).
// ---------------------------------------------------------------------------
__global__ __launch_bounds__(256) void k_apply(const float* __restrict__ resid,
                                               float* __restrict__ out,
                                               const float* __restrict__ salpha,
                                               const float* __restrict__ pbs,
                                               const float* __restrict__ rscale,
                                               const float* __restrict__ sbeta,
                                               const float* __restrict__ hps) {
    const int bn = blockIdx.x;
    const int b = bn >> 10, n = bn & 1023;
    const int tid = threadIdx.x;

    __shared__ float pS[8][24];
    __shared__ float dotS[23];
    __shared__ float wpreS[8], betaS[8], pk3[3];
    __shared__ float Ms[64];

    // gather partials: 192 threads, one (chunk, j) each
    if (tid < 192) {
        int c = tid / 24, j = tid - c * 24;
        float v = 0.0f;
        if (j < 22)       v = g_part[c][bn][j];
        else if (j == 22) v = g_ss[c][bn];
        pS[c][j] = v;
    }
    __syncthreads();
    // fixed-order chunk sums (deterministic)
    if (tid < 23) {
        float v = 0.0f;
        #pragma unroll
        for (int c = 0; c < KC; c++) v += pS[c][tid];
        dotS[tid] = v;
    }
    __syncthreads();
    // scalar stage (split across threads 0..18)
    if (tid < 19) {
        float scale = rsqrtf(fmaxf(dotS[22], 1e-24f)) * 128.0f;  // sqrt(16384)
        if (tid < 8) {
            // wpre[tid] = softmax(ps * dyn_pre + static_alpha[:8])[tid]
            float ps = pbs[0];
            float l[8], mx = -1e30f;
            #pragma unroll
            for (int i = 0; i < 8; i++) {
                l[i] = ps * (scale * dotS[i]) + salpha[i];
                mx = fmaxf(mx, l[i]);
            }
            float sum = 0.0f;
            #pragma unroll
            for (int i = 0; i < 8; i++) sum += expf(l[i] - mx);
            wpreS[tid] = expf(l[tid] - mx) / sum;
        } else if (tid < 16) {
            int t = tid - 8;
            float hp = hps[0];
            betaS[t] = 1.0f / (1.0f + expf(-(hp * (scale * dotS[14 + t]) + sbeta[t])));
        } else {
            int k = tid - 16;
            float rs = rscale[0];
            float c0 = rs * (scale * dotS[8 + 2 * k])     + salpha[8 + 2 * k];
            float c1 = rs * (scale * dotS[8 + 2 * k + 1]) + salpha[8 + 2 * k + 1];
            pk3[k] = 1.0f / (1.0f + expf(c1 - c0));
        }
    }
    __syncthreads();
    // M[s][t] = h[s^t] + beta[t]*wpre[s]
    if (tid < 64) {
        int s = tid >> 3, t = tid & 7, x = s ^ t;
        float f0 = (x & 4) ? (1.0f - pk3[0]) : pk3[0];
        float f1 = (x & 2) ? (1.0f - pk3[1]) : pk3[1];
        float f2 = (x & 1) ? (1.0f - pk3[2]) : pk3[2];
        Ms[tid] = f0 * f1 * f2 + betaS[t] * wpreS[s];
    }
    __syncthreads();

    // ---- unchanged R8 apply body ----
    float M[64];
    #pragma unroll
    for (int i = 0; i < 64; i++) M[i] = Ms[i];

    const size_t base = (size_t)b * 16777216u + (size_t)n * 2048u;
    const int d = blockIdx.y * 1024 + tid * 4;

    float4 acc[8];
    #pragma unroll
    for (int t = 0; t < 8; t++) acc[t] = make_float4(0.f, 0.f, 0.f, 0.f);

    #pragma unroll
    for (int s = 0; s < 8; s++) {
        float4 r4 = *reinterpret_cast<const float4*>(resid + base + (size_t)s * 2097152u + d);
        #pragma unroll
        for (int t = 0; t < 8; t++) {
            float m = M[s * 8 + t];
            acc[t].x += m * r4.x;
            acc[t].y += m * r4.y;
            acc[t].z += m * r4.z;
            acc[t].w += m * r4.w;
        }
    }
    #pragma unroll
    for (int t = 0; t < 8; t++)
        *reinterpret_cast<float4*>(out + base + (size_t)t * 2097152u + d) = acc[t];
}

// ---------------------------------------------------------------------------
extern "C" void kernel_launch(void* const* d_in, const int* in_sizes, int n_in,
                              void* d_out, int out_size) {
    const float* resid  = (const float*)d_in[0];   // residuals (B*S, N, D)
    const float* gamma  = (const float*)d_in[1];   // (S*D,)
    const float* salpha = (const float*)d_in[2];   // (S+T,) = 14
    const float* Wa     = (const float*)d_in[3];   // (S*D, 14)
    const float* pbs    = (const float*)d_in[4];   // (1,)
    const float* rs     = (const float*)d_in[5];   // (1,)
    const float* sbeta  = (const float*)d_in[6];   // (S,) = 8
    const float* Wb     = (const float*)d_in[7];   // (S*D, 8)
    const float* hps    = (const float*)d_in[8];   // scalar
    float* out = (float*)d_out;

    k_prepW<<<(KT_TOT * 12 * 32 + 255) / 256, 256>>>(gamma, Wa, Wb);
    k_reduce<<<dim3(MT, KC), 256>>>(resid);
    k_apply<<<dim3(BN, 2), 256>>>(resid, out, salpha, pbs, rs, sbeta, hps);
}